// round 1
// baseline (speedup 1.0000x reference)
#include <cuda_runtime.h>
#include <math.h>

// Problem constants (fixed by setup_inputs)
#define BATCH 8
#define NQ    300
#define CH    256
#define NLVL  4
#define P_IN  32

__device__ __forceinline__ float warp_sum(float v) {
#pragma unroll
    for (int o = 16; o > 0; o >>= 1) v += __shfl_down_sync(0xffffffffu, v, o);
    return v;
}

__global__ __launch_bounds__(CH, 4)
void sampling3d_kernel(const float* __restrict__ f0,
                       const float* __restrict__ f1,
                       const float* __restrict__ f2,
                       const float* __restrict__ f3,
                       const float* __restrict__ qpos,
                       const float* __restrict__ qcont,
                       const float* __restrict__ Woff,
                       const float* __restrict__ boff,
                       const float* __restrict__ sigma_z,
                       float* __restrict__ out)
{
    const int idx = blockIdx.x;        // b*NQ + n
    const int c   = threadIdx.x;       // channel
    const int b   = idx / NQ;

    __shared__ float s_red[3][8];
    __shared__ float s_off[3];

    // ---- offsets = query_content @ W_off + b_off  (block reduction) ----
    const float q = qcont[(size_t)idx * CH + c];
    float p0 = q * Woff[c * 3 + 0];
    float p1 = q * Woff[c * 3 + 1];
    float p2 = q * Woff[c * 3 + 2];
    p0 = warp_sum(p0); p1 = warp_sum(p1); p2 = warp_sum(p2);
    const int lane = c & 31, wid = c >> 5;
    if (lane == 0) { s_red[0][wid] = p0; s_red[1][wid] = p1; s_red[2][wid] = p2; }
    __syncthreads();
    if (c < 3) {
        float s = boff[c];
#pragma unroll
        for (int w = 0; w < 8; w++) s += s_red[c][w];
        s_off[c] = s;
    }
    __syncthreads();
    const float dx = s_off[0], dy = s_off[1], dz = s_off[2];

    // ---- per-query scalars (redundant across threads; cheap) ----
    const float x = qpos[idx * 4 + 0];
    const float y = qpos[idx * 4 + 1];
    const float z = qpos[idx * 4 + 2];
    const float r = qpos[idx * 4 + 3];
    const float sx = x + dx * exp2f(z - r);
    const float sy = y + dy * exp2f(z + r);
    const float sz = z + dz;
    const float sig = sigma_z[0];
    const float invs = 1.0f / (2.0f * sig * sig);

    float wlv[NLVL];
    float m = -1e30f;
#pragma unroll
    for (int l = 0; l < NLVL; l++) {
        const float d = sz - (float)l;
        wlv[l] = expf(-d * d * invs);
        m = fmaxf(m, wlv[l]);
    }
    float e[NLVL], se = 0.0f;
#pragma unroll
    for (int l = 0; l < NLVL; l++) { e[l] = expf(wlv[l] - m); se += e[l]; }
    const float invse = 1.0f / se;

    // ---- 4-level bilinear-border gather, all loads batched ----
    const float* fptr[NLVL] = { f0, f1, f2, f3 };
    const int    HS[NLVL]   = { 100, 50, 25, 13 };

    float acc = 0.0f;
#pragma unroll
    for (int l = 0; l < NLVL; l++) {
        const int   H  = HS[l];
        const float fH = (float)H;
        const float px = fminf(fmaxf(sx - 0.5f, 0.0f), fH - 1.0f);
        const float py = fminf(fmaxf(sy - 0.5f, 0.0f), fH - 1.0f);
        const float x0f = floorf(px), y0f = floorf(py);
        const float wx = px - x0f, wy = py - y0f;
        const int x0 = (int)x0f, y0 = (int)y0f;
        const int x1 = min(x0 + 1, H - 1);
        const int y1 = min(y0 + 1, H - 1);
        const float* base = fptr[l] + (size_t)(b * CH + c) * H * H;
        const float v00 = __ldg(base + y0 * H + x0);
        const float v01 = __ldg(base + y0 * H + x1);
        const float v10 = __ldg(base + y1 * H + x0);
        const float v11 = __ldg(base + y1 * H + x1);
        const float bil = (v00 * (1.0f - wx) + v01 * wx) * (1.0f - wy)
                        + (v10 * (1.0f - wx) + v11 * wx) * wy;
        acc += (e[l] * invse) * bil;
    }

    // ---- broadcast to all P_IN points (coalesced per-warp stores) ----
    float* o = out + (size_t)idx * P_IN * CH + c;
#pragma unroll
    for (int p = 0; p < P_IN; p++) o[(size_t)p * CH] = acc;
}

extern "C" void kernel_launch(void* const* d_in, const int* in_sizes, int n_in,
                              void* d_out, int out_size)
{
    const float* f0    = (const float*)d_in[0];
    const float* f1    = (const float*)d_in[1];
    const float* f2    = (const float*)d_in[2];
    const float* f3    = (const float*)d_in[3];
    const float* qpos  = (const float*)d_in[4];
    const float* qcont = (const float*)d_in[5];
    const float* Woff  = (const float*)d_in[6];
    const float* boff  = (const float*)d_in[7];
    const float* sigz  = (const float*)d_in[8];
    float* out = (float*)d_out;

    sampling3d_kernel<<<BATCH * NQ, CH>>>(f0, f1, f2, f3, qpos, qcont,
                                          Woff, boff, sigz, out);
}

// round 4
// speedup vs baseline: 1.1087x; 1.1087x over previous
#include <cuda_runtime.h>
#include <math.h>

#define BATCH 8
#define NQ    300
#define CH    256
#define NLVL  4
#define P_IN  32

__device__ __forceinline__ float warp_sum(float v) {
#pragma unroll
    for (int o = 16; o > 0; o >>= 1) v += __shfl_down_sync(0xffffffffu, v, o);
    return v;
}

__global__ __launch_bounds__(CH, 4)
void sampling3d_kernel(const float* __restrict__ f0,
                       const float* __restrict__ f1,
                       const float* __restrict__ f2,
                       const float* __restrict__ f3,
                       const float* __restrict__ qpos,
                       const float* __restrict__ qcont,
                       const float* __restrict__ Woff,
                       const float* __restrict__ boff,
                       const float* __restrict__ sigma_z,
                       float* __restrict__ out)
{
    const int idx = blockIdx.x;        // b*NQ + n
    const int t   = threadIdx.x;
    const int b   = idx / NQ;

    // s_acc first + explicit 16B alignment: float4 reads from it must not trap.
    __shared__ __align__(16) float s_acc[CH];
    __shared__ float s_red[3][8];
    __shared__ float s_off[4];

    // ---- offsets = query_content @ W_off + b_off  (block reduction) ----
    const float q = qcont[(size_t)idx * CH + t];
    float p0 = q * Woff[t * 3 + 0];
    float p1 = q * Woff[t * 3 + 1];
    float p2 = q * Woff[t * 3 + 2];
    p0 = warp_sum(p0); p1 = warp_sum(p1); p2 = warp_sum(p2);
    const int lane = t & 31, wid = t >> 5;
    if (lane == 0) { s_red[0][wid] = p0; s_red[1][wid] = p1; s_red[2][wid] = p2; }
    __syncthreads();
    if (t < 3) {
        float s = boff[t];
#pragma unroll
        for (int w = 0; w < 8; w++) s += s_red[t][w];
        s_off[t] = s;
    }
    __syncthreads();
    const float dx = s_off[0], dy = s_off[1], dz = s_off[2];

    // ---- per-query scalars (uniform across block; cheap redundancy) ----
    const float x = qpos[idx * 4 + 0];
    const float y = qpos[idx * 4 + 1];
    const float z = qpos[idx * 4 + 2];
    const float r = qpos[idx * 4 + 3];
    const float sx = x + dx * exp2f(z - r);
    const float sy = y + dy * exp2f(z + r);
    const float sz = z + dz;
    const float sig = sigma_z[0];
    const float invs = 1.0f / (2.0f * sig * sig);

    float g[NLVL];
    float m = -1e30f;
#pragma unroll
    for (int l = 0; l < NLVL; l++) {
        const float d = sz - (float)l;
        g[l] = expf(-d * d * invs);
        m = fmaxf(m, g[l]);
    }
    float e[NLVL], se = 0.0f;
#pragma unroll
    for (int l = 0; l < NLVL; l++) { e[l] = expf(g[l] - m); se += e[l]; }
    const float invse = 1.0f / se;
    float zw[NLVL];
#pragma unroll
    for (int l = 0; l < NLVL; l++) zw[l] = e[l] * invse;

    // ---- corner-in-lane gather: lane = 4*chan_group + corner ----
    // corners of one channel sit in 4 adjacent lanes -> (y,x0)/(y,x1)
    // share a 128B line and coalesce into one L1tex wavefront.
    const float* fptr[NLVL] = { f0, f1, f2, f3 };
    const int    HS[NLVL]   = { 100, 50, 25, 13 };

    const int corner = t & 3;          // 0:(y0,x0) 1:(y0,x1) 2:(y1,x0) 3:(y1,x1)
    const int cg     = t >> 2;         // channel group 0..63

    float acc0 = 0.f, acc1 = 0.f, acc2 = 0.f, acc3 = 0.f;
#pragma unroll
    for (int l = 0; l < NLVL; l++) {
        const int   H  = HS[l];
        const int   HH = H * H;
        const float fH = (float)H;
        const float px = fminf(fmaxf(sx - 0.5f, 0.0f), fH - 1.0f);
        const float py = fminf(fmaxf(sy - 0.5f, 0.0f), fH - 1.0f);
        const float x0f = floorf(px), y0f = floorf(py);
        const float wx = px - x0f, wy = py - y0f;
        const int x0 = (int)x0f, y0 = (int)y0f;
        const int x1 = min(x0 + 1, H - 1);
        const int y1 = min(y0 + 1, H - 1);

        const int   xsel = (corner & 1) ? x1 : x0;
        const int   ysel = (corner & 2) ? y1 : y0;
        const float wsel = ((corner & 1) ? wx : 1.0f - wx)
                         * ((corner & 2) ? wy : 1.0f - wy) * zw[l];

        const float* base = fptr[l] + (size_t)b * CH * HH + ysel * H + xsel;
        acc0 += wsel * __ldg(base + (size_t)(cg      ) * HH);
        acc1 += wsel * __ldg(base + (size_t)(cg +  64) * HH);
        acc2 += wsel * __ldg(base + (size_t)(cg + 128) * HH);
        acc3 += wsel * __ldg(base + (size_t)(cg + 192) * HH);
    }

    // quad butterfly: sum the 4 corners (linear, so done once after all levels)
    acc0 += __shfl_xor_sync(0xffffffffu, acc0, 1);
    acc0 += __shfl_xor_sync(0xffffffffu, acc0, 2);
    acc1 += __shfl_xor_sync(0xffffffffu, acc1, 1);
    acc1 += __shfl_xor_sync(0xffffffffu, acc1, 2);
    acc2 += __shfl_xor_sync(0xffffffffu, acc2, 1);
    acc2 += __shfl_xor_sync(0xffffffffu, acc2, 2);
    acc3 += __shfl_xor_sync(0xffffffffu, acc3, 1);
    acc3 += __shfl_xor_sync(0xffffffffu, acc3, 2);

    if (corner == 0) {
        s_acc[cg      ] = acc0;
        s_acc[cg +  64] = acc1;
        s_acc[cg + 128] = acc2;
        s_acc[cg + 192] = acc3;
    }
    __syncthreads();

    // ---- broadcast to P_IN points with 128-bit stores ----
    const float4 v = ((const float4*)s_acc)[t & 63];
    float4* ov = (float4*)out + (size_t)idx * (P_IN * CH / 4);
#pragma unroll
    for (int i = 0; i < 8; i++)
        ov[t + i * CH] = v;
}

extern "C" void kernel_launch(void* const* d_in, const int* in_sizes, int n_in,
                              void* d_out, int out_size)
{
    const float* f0    = (const float*)d_in[0];
    const float* f1    = (const float*)d_in[1];
    const float* f2    = (const float*)d_in[2];
    const float* f3    = (const float*)d_in[3];
    const float* qpos  = (const float*)d_in[4];
    const float* qcont = (const float*)d_in[5];
    const float* Woff  = (const float*)d_in[6];
    const float* boff  = (const float*)d_in[7];
    const float* sigz  = (const float*)d_in[8];
    float* out = (float*)d_out;

    sampling3d_kernel<<<BATCH * NQ, CH>>>(f0, f1, f2, f3, qpos, qcont,
                                          Woff, boff, sigz, out);
}

// round 6
// speedup vs baseline: 1.1164x; 1.0069x over previous
#include <cuda_runtime.h>
#include <math.h>

#define BATCH 8
#define NQ    300
#define CH    256
#define NLVL  4
#define P_IN  32

__device__ __forceinline__ float warp_sum(float v) {
#pragma unroll
    for (int o = 16; o > 0; o >>= 1) v += __shfl_down_sync(0xffffffffu, v, o);
    return v;
}

__global__ __launch_bounds__(CH, 6)
void sampling3d_kernel(const float* __restrict__ f0,
                       const float* __restrict__ f1,
                       const float* __restrict__ f2,
                       const float* __restrict__ f3,
                       const float* __restrict__ qpos,
                       const float* __restrict__ qcont,
                       const float* __restrict__ Woff,
                       const float* __restrict__ boff,
                       const float* __restrict__ sigma_z,
                       float* __restrict__ out)
{
    const int idx = blockIdx.x;        // b*NQ + n
    const int t   = threadIdx.x;
    const int b   = idx / NQ;

    __shared__ __align__(16) float s_acc[CH];
    __shared__ float s_red[3][8];
    __shared__ float s_off[4];

    // ---- offsets = query_content @ W_off + b_off  (block reduction) ----
    const float q = qcont[(size_t)idx * CH + t];
    float p0 = q * Woff[t * 3 + 0];
    float p1 = q * Woff[t * 3 + 1];
    float p2 = q * Woff[t * 3 + 2];
    p0 = warp_sum(p0); p1 = warp_sum(p1); p2 = warp_sum(p2);
    const int lane = t & 31, wid = t >> 5;
    if (lane == 0) { s_red[0][wid] = p0; s_red[1][wid] = p1; s_red[2][wid] = p2; }
    __syncthreads();
    if (t < 3) {
        float s = boff[t];
#pragma unroll
        for (int w = 0; w < 8; w++) s += s_red[t][w];
        s_off[t] = s;
    }
    __syncthreads();
    const float dx = s_off[0], dy = s_off[1], dz = s_off[2];

    // ---- per-query scalars (uniform across block) ----
    const float x = qpos[idx * 4 + 0];
    const float y = qpos[idx * 4 + 1];
    const float z = qpos[idx * 4 + 2];
    const float r = qpos[idx * 4 + 3];
    const float sx = x + dx * exp2f(z - r);
    const float sy = y + dy * exp2f(z + r);
    const float sz = z + dz;
    const float sig = sigma_z[0];
    const float invs = 1.0f / (2.0f * sig * sig);

    float g[NLVL];
    float m = -1e30f;
#pragma unroll
    for (int l = 0; l < NLVL; l++) {
        const float d = sz - (float)l;
        g[l] = expf(-d * d * invs);
        m = fmaxf(m, g[l]);
    }
    float e[NLVL], se = 0.0f;
#pragma unroll
    for (int l = 0; l < NLVL; l++) { e[l] = expf(g[l] - m); se += e[l]; }
    const float invse = 1.0f / se;
    float zw[NLVL];
#pragma unroll
    for (int l = 0; l < NLVL; l++) zw[l] = e[l] * invse;

    // ---- corner-in-lane gather: lane = 4*chan_group + corner ----
    const float* fptr[NLVL] = { f0, f1, f2, f3 };
    const int    HS[NLVL]   = { 100, 50, 25, 13 };

    const int corner = t & 3;          // 0:(y0,x0) 1:(y0,x1) 2:(y1,x0) 3:(y1,x1)
    const int cg     = t >> 2;         // channel group 0..63

    float acc0 = 0.f, acc1 = 0.f, acc2 = 0.f, acc3 = 0.f;
#pragma unroll
    for (int l = 0; l < NLVL; l++) {
        const int   H  = HS[l];
        const int   HH = H * H;
        const float fH = (float)H;
        const float px = fminf(fmaxf(sx - 0.5f, 0.0f), fH - 1.0f);
        const float py = fminf(fmaxf(sy - 0.5f, 0.0f), fH - 1.0f);
        const float x0f = floorf(px), y0f = floorf(py);
        const float wx = px - x0f, wy = py - y0f;
        const int x0 = (int)x0f, y0 = (int)y0f;
        const int x1 = min(x0 + 1, H - 1);
        const int y1 = min(y0 + 1, H - 1);

        const int   xsel = (corner & 1) ? x1 : x0;
        const int   ysel = (corner & 2) ? y1 : y0;
        const float wsel = ((corner & 1) ? wx : 1.0f - wx)
                         * ((corner & 2) ? wy : 1.0f - wy) * zw[l];

        const float* base = fptr[l] + (size_t)b * CH * HH + ysel * H + xsel;
        acc0 += wsel * __ldg(base + (size_t)(cg      ) * HH);
        acc1 += wsel * __ldg(base + (size_t)(cg +  64) * HH);
        acc2 += wsel * __ldg(base + (size_t)(cg + 128) * HH);
        acc3 += wsel * __ldg(base + (size_t)(cg + 192) * HH);
    }

    // quad butterfly over the 4 corners
    acc0 += __shfl_xor_sync(0xffffffffu, acc0, 1);
    acc0 += __shfl_xor_sync(0xffffffffu, acc0, 2);
    acc1 += __shfl_xor_sync(0xffffffffu, acc1, 1);
    acc1 += __shfl_xor_sync(0xffffffffu, acc1, 2);
    acc2 += __shfl_xor_sync(0xffffffffu, acc2, 1);
    acc2 += __shfl_xor_sync(0xffffffffu, acc2, 2);
    acc3 += __shfl_xor_sync(0xffffffffu, acc3, 1);
    acc3 += __shfl_xor_sync(0xffffffffu, acc3, 2);

    if (corner == 0) {
        s_acc[cg      ] = acc0;
        s_acc[cg +  64] = acc1;
        s_acc[cg + 128] = acc2;
        s_acc[cg + 192] = acc3;
    }
    __syncthreads();

    // ---- broadcast to P_IN points, evict-first streaming stores ----
    // (__stcs keeps the 108MB feat working set resident in L2)
    const float4 v = ((const float4*)s_acc)[t & 63];
    float4* ov = (float4*)out + (size_t)idx * (P_IN * CH / 4);
#pragma unroll
    for (int i = 0; i < 8; i++)
        __stcs(&ov[t + i * CH], v);
}

extern "C" void kernel_launch(void* const* d_in, const int* in_sizes, int n_in,
                              void* d_out, int out_size)
{
    const float* f0    = (const float*)d_in[0];
    const float* f1    = (const float*)d_in[1];
    const float* f2    = (const float*)d_in[2];
    const float* f3    = (const float*)d_in[3];
    const float* qpos  = (const float*)d_in[4];
    const float* qcont = (const float*)d_in[5];
    const float* Woff  = (const float*)d_in[6];
    const float* boff  = (const float*)d_in[7];
    const float* sigz  = (const float*)d_in[8];
    float* out = (float*)d_out;

    sampling3d_kernel<<<BATCH * NQ, CH>>>(f0, f1, f2, f3, qpos, qcont,
                                          Woff, boff, sigz, out);
}